// round 10
// baseline (speedup 1.0000x reference)
#include <cuda_runtime.h>
#include <cuda_bf16.h>
#include <math.h>
#include <stdint.h>

#define NN     20000
#define TT     32
#define INP    64
#define HH     128
#define G3     384
#define SS     64
#define EINTRA 640000
#define EINTER 4096

// ---------------- scratch (static device globals; no allocs) ----------------
__device__ __align__(128) float g_gi[(size_t)NN*TT*G3];            // layer0 gi, 983 MB
__device__ __align__(128) __nv_bfloat16 g_xb[(size_t)NN*TT*2*INP]; // x as hi|lo
__device__ __align__(128) float g_g01[(size_t)NN*768];             // [gh0 | gi1] fused
__device__ __align__(128) float g_gh1[(size_t)NN*G3];
__device__ __align__(128) float g_h0[(size_t)NN*HH];
__device__ __align__(128) float g_h1[(size_t)NN*HH];
__device__ __align__(128) __nv_bfloat16 g_hb0[(size_t)NN*2*HH];
__device__ __align__(128) __nv_bfloat16 g_hb1[(size_t)NN*2*HH];
__device__ __align__(128) float g_hlin[(size_t)NN*HH];
__device__ __align__(128) float g_acc[(size_t)NN*HH];
__device__ __align__(128) __nv_bfloat16 g_wb_ih0[G3*2*INP];
__device__ __align__(128) __nv_bfloat16 g_wb_s0[2*G3*2*HH];        // [Whh0 ; Wih1] stacked, 768x256
__device__ __align__(128) __nv_bfloat16 g_wb_hh1[G3*2*HH];
__device__ __align__(128) __nv_bfloat16 g_wb_intra[HH*2*HH];
__device__ __align__(128) __nv_bfloat16 g_wb_inter[HH*2*HH];
__device__ float    g_es[NN];
__device__ float    g_ed[NN];
__device__ float    g_m[NN];
__device__ unsigned g_deg[NN];
__device__ unsigned g_off[NN];
__device__ unsigned g_work[NN];
__device__ int      g_csrc[EINTRA];
__device__ float    g_ev[EINTRA];
__device__ unsigned g_pu[SS*HH];
__device__ __align__(128) float g_pool[SS*HH];
__device__ __align__(128) __nv_bfloat16 g_poolb[SS*2*HH];
__device__ __align__(128) float g_shlin[SS*HH];
__device__ __align__(128) float g_sacc[SS*HH];

// ---------------- helpers ----------------
__device__ __forceinline__ uint32_t smem_u32(const void* p) {
    uint32_t a;
    asm("{ .reg .u64 t; cvta.to.shared.u64 t, %1; cvt.u32.u64 %0, t; }" : "=r"(a) : "l"(p));
    return a;
}
__device__ __forceinline__ unsigned fkey(float f) {
    unsigned u = __float_as_uint(f);
    return (u & 0x80000000u) ? ~u : (u | 0x80000000u);
}
__device__ __forceinline__ float funkey(unsigned k) {
    return (k & 0x80000000u) ? __uint_as_float(k & 0x7fffffffu)
                             : __uint_as_float(~k);
}
__device__ __forceinline__ float lrelu(float x) { return x > 0.f ? x : 0.2f * x; }

__device__ __forceinline__ void cp_async16(uint32_t saddr, const void* gaddr, int srcBytes) {
    asm volatile("cp.async.cg.shared.global [%0], [%1], 16, %2;"
                 :: "r"(saddr), "l"(gaddr), "r"(srcBytes) : "memory");
}
__device__ __forceinline__ void cp_commit() {
    asm volatile("cp.async.commit_group;" ::: "memory");
}
template <int N>
__device__ __forceinline__ void cp_wait() {
    asm volatile("cp.async.wait_group %0;" :: "n"(N) : "memory");
}
__device__ __forceinline__ void ldmatrix_x4(uint32_t* r, uint32_t addr) {
    asm volatile("ldmatrix.sync.aligned.m8n8.x4.shared.b16 {%0,%1,%2,%3}, [%4];"
                 : "=r"(r[0]), "=r"(r[1]), "=r"(r[2]), "=r"(r[3]) : "r"(addr));
}
__device__ __forceinline__ void mma16816(float* d, const uint32_t* a, uint32_t b0, uint32_t b1) {
    asm volatile(
        "mma.sync.aligned.m16n8k16.row.col.f32.bf16.bf16.f32 "
        "{%0,%1,%2,%3}, {%4,%5,%6,%7}, {%8,%9}, {%0,%1,%2,%3};"
        : "+f"(d[0]), "+f"(d[1]), "+f"(d[2]), "+f"(d[3])
        : "r"(a[0]), "r"(a[1]), "r"(a[2]), "r"(a[3]), "r"(b0), "r"(b1));
}

// ---------------- misc kernels ----------------
__global__ void zerof_k(float* p, int n) {
    int i = blockIdx.x * blockDim.x + threadIdx.x;
    if (i < n) p[i] = 0.f;
}
__global__ void zerou_k(unsigned* p, int n) {
    int i = blockIdx.x * blockDim.x + threadIdx.x;
    if (i < n) p[i] = 0u;
}
// split fp32 [rows,K] -> bf16 [rows, 2K] as [hi | lo]
__global__ void convw_k(const float* __restrict__ W, __nv_bfloat16* __restrict__ Wb,
                        int rows, int K) {
    int idx = blockIdx.x * blockDim.x + threadIdx.x;
    if (idx >= rows * K) return;
    int r = idx / K, c = idx % K;
    float v = W[idx];
    __nv_bfloat16 hi = __float2bfloat16(v);
    __nv_bfloat16 lo = __float2bfloat16(v - __bfloat162float(hi));
    Wb[(size_t)r * 2 * K + c]     = hi;
    Wb[(size_t)r * 2 * K + K + c] = lo;
}

// ---------------- tensor-core GEMM body (mma.sync bf16): C = split(A) @ split(B)^T
__device__ __forceinline__ void gemm_body(
    char* smbuf,
    const __nv_bfloat16* __restrict__ Ab, int ldA,
    const __nv_bfloat16* __restrict__ Bb,
    float* __restrict__ C, int M, int Nc, int K, int bm, int bn)
{
    const uint32_t sb = smem_u32(smbuf);
    const int tid = threadIdx.x;
    const int wid = tid >> 5, lane = tid & 31;
    const int wm = wid & 3;
    const int wn = wid >> 2;
    const int ldB = 2 * K;

    const int cpk = K >> 5;
    const int nk = 3 * cpk;

    float d[2][8][4];
#pragma unroll
    for (int i = 0; i < 2; i++)
#pragma unroll
        for (int j = 0; j < 8; j++)
#pragma unroll
            for (int q = 0; q < 4; q++) d[i][j][q] = 0.f;

    auto issue_loads = [&](int kb, int s) {
        const int seg = kb / cpk, kc = kb - seg * cpk;
        const int acol = (seg == 1 ? K : 0) + (kc << 5);
        const int bcol = (seg == 2 ? K : 0) + (kc << 5);
        const __nv_bfloat16* Abase = Ab + acol;
        const __nv_bfloat16* Bbase = Bb + bcol;
        const uint32_t sA = sb + s * 16384;
        const uint32_t sB = sA + 8192;
#pragma unroll
        for (int i = 0; i < 2; i++) {
            int cid = tid + (i << 8);
            int r = cid >> 2, c = cid & 3;
            uint32_t soff = (uint32_t)(r << 6) + (uint32_t)((c ^ ((r >> 1) & 3)) << 4);
            int arow = bm + r;
            const char* ga = (const char*)(Abase + (size_t)(arow < M ? arow : 0) * ldA) + (c << 4);
            cp_async16(sA + soff, ga, arow < M ? 16 : 0);
            const char* gb = (const char*)(Bbase + (size_t)(bn + r) * ldB) + (c << 4);
            cp_async16(sB + soff, gb, 16);
        }
        cp_commit();
    };

    issue_loads(0, 0);

    for (int kb = 0; kb < nk; kb++) {
        const int s = kb & 1;
        if (kb + 1 < nk) issue_loads(kb + 1, s ^ 1);
        if (kb + 1 < nk) cp_wait<1>(); else cp_wait<0>();
        __syncthreads();

        const uint32_t sA = sb + s * 16384;
        const uint32_t sB = sA + 8192;
        const int lr = lane & 15;
        const int lk = (lane >> 4) << 4;
#pragma unroll
        for (int k16 = 0; k16 < 2; k16++) {
            const int kby = (k16 << 5) + lk;
            const int csel = kby >> 4;
            uint32_t a[2][4], bf[4][4];
#pragma unroll
            for (int mt = 0; mt < 2; mt++) {
                int r = wm * 32 + mt * 16 + lr;
                uint32_t addr = sA + (uint32_t)(r << 6) + (uint32_t)((csel ^ ((r >> 1) & 3)) << 4);
                ldmatrix_x4(a[mt], addr);
            }
#pragma unroll
            for (int p = 0; p < 4; p++) {
                int r = wn * 64 + p * 16 + lr;
                uint32_t addr = sB + (uint32_t)(r << 6) + (uint32_t)((csel ^ ((r >> 1) & 3)) << 4);
                ldmatrix_x4(bf[p], addr);
            }
#pragma unroll
            for (int mt = 0; mt < 2; mt++)
#pragma unroll
                for (int nt = 0; nt < 8; nt++) {
                    int p = nt >> 1, hi = nt & 1;
                    mma16816(d[mt][nt], a[mt], bf[p][hi], bf[p][2 + hi]);
                }
        }
        __syncthreads();
    }

    const int gr = lane >> 2;
    const int gc = (lane & 3) << 1;
#pragma unroll
    for (int mt = 0; mt < 2; mt++) {
        int r0 = bm + wm * 32 + mt * 16 + gr;
#pragma unroll
        for (int nt = 0; nt < 8; nt++) {
            int cc = bn + wn * 64 + nt * 8 + gc;
            if (r0 < M)
                *(float2*)(C + (size_t)r0 * Nc + cc) = make_float2(d[mt][nt][0], d[mt][nt][1]);
            if (r0 + 8 < M)
                *(float2*)(C + (size_t)(r0 + 8) * Nc + cc) = make_float2(d[mt][nt][2], d[mt][nt][3]);
        }
    }
}

// single-problem GEMM kernel
__global__ void __launch_bounds__(256) gemm_mma_k(
    const __nv_bfloat16* __restrict__ Ab, int ldA,
    const __nv_bfloat16* __restrict__ Bb,
    float* __restrict__ C, int M, int Nc, int K)
{
    __shared__ __align__(16) char smbuf[32768];
    gemm_body(smbuf, Ab, ldA, Bb, C, M, Nc, K, blockIdx.y * 128, blockIdx.x * 128);
}

// recurrent-step GEMM: bx 0..5: [gh0|gi1] = hb0 @ [Whh0;Wih1]^T (Nc=768);
//                      bx 6..8: gh1 = hb1 @ Whh1^T (Nc=384), only if act1.
__global__ void __launch_bounds__(256) gemm2_k(
    const __nv_bfloat16* __restrict__ hb0,
    const __nv_bfloat16* __restrict__ hb1,
    const __nv_bfloat16* __restrict__ Bs0,
    const __nv_bfloat16* __restrict__ Bhh1,
    float* __restrict__ g01, float* __restrict__ gh1, int act1)
{
    __shared__ __align__(16) char smbuf[32768];
    const int bx = blockIdx.x;
    const int bm = blockIdx.y * 128;
    if (bx < 6) {
        gemm_body(smbuf, hb0, 2 * HH, Bs0, g01, NN, 768, HH, bm, bx * 128);
    } else {
        if (!act1) return;
        gemm_body(smbuf, hb1, 2 * HH, Bhh1, gh1, NN, G3, HH, bm, (bx - 6) * 128);
    }
}

// ---------------- dual-layer GRU pointwise cell ----------------
__global__ void cell2_k(const float* __restrict__ gi0, const float* __restrict__ g01,
                        const float* __restrict__ gh1,
                        const float* __restrict__ bih0, const float* __restrict__ bhh0,
                        float* __restrict__ h0, __nv_bfloat16* __restrict__ hb0,
                        const float* __restrict__ bih1, const float* __restrict__ bhh1,
                        float* __restrict__ h1, __nv_bfloat16* __restrict__ hb1,
                        int t0, int act0, int act1) {
    int idx = blockIdx.x * blockDim.x + threadIdx.x;
    if (idx >= NN * HH) return;
    int i = idx >> 7;
    int j = idx & 127;
    if (blockIdx.y == 0) {
        if (!act0) return;
        size_t mg = ((size_t)i * TT + t0) * G3;
        size_t hg = (size_t)i * 768;
        float ir  = gi0[mg + j]          + bih0[j];
        float iz  = gi0[mg + HH + j]     + bih0[HH + j];
        float inn = gi0[mg + 2 * HH + j] + bih0[2 * HH + j];
        float hr  = g01[hg + j]          + bhh0[j];
        float hz  = g01[hg + HH + j]     + bhh0[HH + j];
        float hn  = g01[hg + 2 * HH + j] + bhh0[2 * HH + j];
        float r = 1.f / (1.f + expf(-(ir + hr)));
        float z = 1.f / (1.f + expf(-(iz + hz)));
        float n = tanhf(inn + r * hn);
        float hold = h0[idx];
        float hnew = (1.f - z) * n + z * hold;
        h0[idx] = hnew;
        __nv_bfloat16 hi = __float2bfloat16(hnew);
        __nv_bfloat16 lo = __float2bfloat16(hnew - __bfloat162float(hi));
        hb0[(size_t)i * 256 + j]      = hi;
        hb0[(size_t)i * 256 + HH + j] = lo;
    } else {
        if (!act1) return;
        size_t ig = (size_t)i * 768 + 384;     // gi1 slice of g01
        size_t hg = (size_t)i * G3;
        float ir  = g01[ig + j]          + bih1[j];
        float iz  = g01[ig + HH + j]     + bih1[HH + j];
        float inn = g01[ig + 2 * HH + j] + bih1[2 * HH + j];
        float hr  = gh1[hg + j]          + bhh1[j];
        float hz  = gh1[hg + HH + j]     + bhh1[HH + j];
        float hn  = gh1[hg + 2 * HH + j] + bhh1[2 * HH + j];
        float r = 1.f / (1.f + expf(-(ir + hr)));
        float z = 1.f / (1.f + expf(-(iz + hz)));
        float n = tanhf(inn + r * hn);
        float hold = h1[idx];
        float hnew = (1.f - z) * n + z * hold;
        h1[idx] = hnew;
        __nv_bfloat16 hi = __float2bfloat16(hnew);
        __nv_bfloat16 lo = __float2bfloat16(hnew - __bfloat162float(hi));
        hb1[(size_t)i * 256 + j]      = hi;
        hb1[(size_t)i * 256 + HH + j] = lo;
    }
}

// ---------------- GAT kernels (CSR, no fp32 atomics) ----------------
__global__ void gat_scores_k(const float* __restrict__ hlin,
                             const float* __restrict__ asrc, const float* __restrict__ adst,
                             float* __restrict__ es, float* __restrict__ ed, int n) {
    int g = blockIdx.x * blockDim.x + threadIdx.x;
    int node = g >> 5;
    int lane = g & 31;
    if (node >= n) return;
    float4 h4 = reinterpret_cast<const float4*>(hlin + (size_t)node * HH)[lane];
    float4 a4 = reinterpret_cast<const float4*>(asrc)[lane];
    float4 d4 = reinterpret_cast<const float4*>(adst)[lane];
    float s = h4.x * a4.x + h4.y * a4.y + h4.z * a4.z + h4.w * a4.w;
    float d = h4.x * d4.x + h4.y * d4.y + h4.z * d4.z + h4.w * d4.w;
#pragma unroll
    for (int o = 16; o; o >>= 1) {
        s += __shfl_xor_sync(0xffffffffu, s, o);
        d += __shfl_xor_sync(0xffffffffu, d, o);
    }
    if (lane == 0) {
        es[node] = s;
        ed[node] = d;
    }
}

__global__ void hist_k(const int* __restrict__ ei, unsigned* __restrict__ deg, int E) {
    int e = blockIdx.x * blockDim.x + threadIdx.x;
    if (e < E) atomicAdd(&deg[ei[E + e]], 1u);
}

// one block, 1024 threads: exclusive scan deg[0..n) -> off, copy to work
__global__ void __launch_bounds__(1024) scan_k(const unsigned* __restrict__ deg,
                                               unsigned* __restrict__ off,
                                               unsigned* __restrict__ work, int n) {
    __shared__ unsigned part[1024];
    int t = threadIdx.x;
    int chunk = (n + 1023) / 1024;
    int b = t * chunk;
    int e = b + chunk < n ? b + chunk : n;
    unsigned s = 0;
    for (int i = b; i < e; i++) s += deg[i];
    part[t] = s;
    __syncthreads();
    for (int o = 1; o < 1024; o <<= 1) {
        unsigned v = (t >= o) ? part[t - o] : 0u;
        __syncthreads();
        part[t] += v;
        __syncthreads();
    }
    unsigned run = (t == 0) ? 0u : part[t - 1];
    for (int i = b; i < e; i++) {
        unsigned d = deg[i];
        off[i] = run;
        work[i] = run;
        run += d;
    }
}

__global__ void scatter_k(const int* __restrict__ ei, unsigned* __restrict__ work,
                          int* __restrict__ csrc, int E) {
    int e = blockIdx.x * blockDim.x + threadIdx.x;
    if (e >= E) return;
    int s = ei[e];
    int d = ei[E + e];
    unsigned p = atomicAdd(&work[d], 1u);
    csrc[p] = s;
}

// warp per node: segment max (incl. self loop) + per-edge leaky-relu scores
__global__ void csr_max_k(const int* __restrict__ csrc, const unsigned* __restrict__ off,
                          const unsigned* __restrict__ deg,
                          const float* __restrict__ es, const float* __restrict__ ed,
                          float* __restrict__ ev, float* __restrict__ m, int n) {
    int g = blockIdx.x * blockDim.x + threadIdx.x;
    int node = g >> 5;
    int lane = g & 31;
    if (node >= n) return;
    float edv = ed[node];
    float mx = lrelu(es[node] + edv);           // self loop
    unsigned o = off[node], dg = deg[node];
    for (unsigned k = lane; k < dg; k += 32) {
        float v = lrelu(es[csrc[o + k]] + edv);
        ev[o + k] = v;
        mx = fmaxf(mx, v);
    }
#pragma unroll
    for (int o2 = 16; o2; o2 >>= 1) mx = fmaxf(mx, __shfl_xor_sync(0xffffffffu, mx, o2));
    if (lane == 0) m[node] = mx;
}

// warp per node: softmax-weighted aggregation, bias, final write (no atomics)
__global__ void csr_agg_k(const int* __restrict__ csrc, const unsigned* __restrict__ off,
                          const unsigned* __restrict__ deg,
                          const float* __restrict__ es, const float* __restrict__ ed,
                          const float* __restrict__ ev, const float* __restrict__ m,
                          const float* __restrict__ hlin, const float* __restrict__ bias,
                          float* __restrict__ outp, int n) {
    int g = blockIdx.x * blockDim.x + threadIdx.x;
    int node = g >> 5;
    int lane = g & 31;
    if (node >= n) return;
    float mv = m[node];
    float w0 = expf(lrelu(es[node] + ed[node]) - mv);
    float den = w0;
    float4 hv = reinterpret_cast<const float4*>(hlin + (size_t)node * HH)[lane];
    float4 a = make_float4(w0 * hv.x, w0 * hv.y, w0 * hv.z, w0 * hv.w);
    unsigned o = off[node], dg = deg[node];
    for (unsigned k = 0; k < dg; k++) {
        float w = expf(ev[o + k] - mv);
        int s = csrc[o + k];
        float4 h4 = reinterpret_cast<const float4*>(hlin + (size_t)s * HH)[lane];
        a.x += w * h4.x; a.y += w * h4.y; a.z += w * h4.z; a.w += w * h4.w;
        den += w;
    }
    float4 b4 = reinterpret_cast<const float4*>(bias)[lane];
    float inv = 1.f / den;
    reinterpret_cast<float4*>(outp + (size_t)node * HH)[lane] =
        make_float4(a.x * inv + b4.x, a.y * inv + b4.y, a.z * inv + b4.z, a.w * inv + b4.w);
}

// ---------------- sector max pool ----------------
__global__ void pool_max_k(const float* __restrict__ x, const int* __restrict__ sid,
                           unsigned* __restrict__ pu) {
    int idx = blockIdx.x * blockDim.x + threadIdx.x;
    if (idx >= NN * HH) return;
    int i = idx >> 7;
    int j = idx & 127;
    atomicMax(&pu[sid[i] * HH + j], fkey(x[idx]));
}
__global__ void pool_conv_k(const unsigned* __restrict__ pu, float* __restrict__ p,
                            __nv_bfloat16* __restrict__ pb) {
    int idx = blockIdx.x * blockDim.x + threadIdx.x;
    if (idx >= SS * HH) return;
    int r = idx >> 7, j = idx & 127;
    float v = funkey(pu[idx]);
    p[idx] = v;
    __nv_bfloat16 hi = __float2bfloat16(v);
    __nv_bfloat16 lo = __float2bfloat16(v - __bfloat162float(hi));
    pb[(size_t)r * 2 * HH + j]      = hi;
    pb[(size_t)r * 2 * HH + HH + j] = lo;
}

// ---------------- fusion head ----------------
__global__ void fusion_k(const float* __restrict__ seq, const float* __restrict__ intra,
                         const float* __restrict__ inter, const int* __restrict__ sid,
                         const float* __restrict__ fw, const float* __restrict__ fb,
                         float* __restrict__ out) {
    int g = blockIdx.x * blockDim.x + threadIdx.x;
    int i = g >> 5;
    int lane = g & 31;
    if (i >= NN) return;
    int sc = sid[i];
    const float4* s4 = reinterpret_cast<const float4*>(seq + (size_t)i * HH);
    const float4* i4 = reinterpret_cast<const float4*>(intra + (size_t)i * HH);
    const float4* e4 = reinterpret_cast<const float4*>(inter + (size_t)sc * HH);
    const float4* w4 = reinterpret_cast<const float4*>(fw);
    float sum = 0.f;
    float4 a, b;
    a = s4[lane]; b = w4[lane];
    sum += a.x * b.x + a.y * b.y + a.z * b.z + a.w * b.w;
    a = i4[lane]; b = w4[32 + lane];
    sum += a.x * b.x + a.y * b.y + a.z * b.z + a.w * b.w;
    a = e4[lane]; b = w4[64 + lane];
    sum += a.x * b.x + a.y * b.y + a.z * b.z + a.w * b.w;
#pragma unroll
    for (int o = 16; o; o >>= 1) sum += __shfl_xor_sync(0xffffffffu, sum, o);
    if (lane == 0) out[i] = sum + fb[0];
}

// ---------------- host ----------------
static inline void launch_gemm(const __nv_bfloat16* Ab, const __nv_bfloat16* Bb,
                               float* C, int M, int Nc, int K) {
    dim3 grid(Nc / 128, (M + 127) / 128);
    gemm_mma_k<<<grid, 256>>>(Ab, 2 * K, Bb, C, M, Nc, K);
}

extern "C" void kernel_launch(void* const* d_in, const int* in_sizes, int n_in,
                              void* d_out, int out_size) {
    const float* x        = (const float*)d_in[0];
    const int*   ei_intra = (const int*)d_in[1];
    const int*   ei_inter = (const int*)d_in[2];
    const int*   sid      = (const int*)d_in[3];
    const float* w_ih0 = (const float*)d_in[4];
    const float* w_hh0 = (const float*)d_in[5];
    const float* b_ih0 = (const float*)d_in[6];
    const float* b_hh0 = (const float*)d_in[7];
    const float* w_ih1 = (const float*)d_in[8];
    const float* w_hh1 = (const float*)d_in[9];
    const float* b_ih1 = (const float*)d_in[10];
    const float* b_hh1 = (const float*)d_in[11];
    const float* intra_W  = (const float*)d_in[12];
    const float* a_src_i  = (const float*)d_in[13];
    const float* a_dst_i  = (const float*)d_in[14];
    const float* bias_i   = (const float*)d_in[15];
    const float* inter_W  = (const float*)d_in[16];
    const float* a_src_e  = (const float*)d_in[17];
    const float* a_dst_e  = (const float*)d_in[18];
    const float* bias_e   = (const float*)d_in[19];
    const float* fw       = (const float*)d_in[20];
    const float* fb       = (const float*)d_in[21];
    float* out = (float*)d_out;

    float *gi, *g01, *gh1, *h0, *h1, *hlin, *acc;
    float *es, *ed, *m, *ev, *pool, *shlin, *sacc;
    __nv_bfloat16 *xb, *hb0, *hb1, *wb_ih0, *wb_s0, *wb_hh1, *wb_a, *wb_e, *poolb;
    unsigned *deg, *off, *work, *pu;
    int *csrc;
    cudaGetSymbolAddress((void**)&gi, g_gi);
    cudaGetSymbolAddress((void**)&xb, g_xb);
    cudaGetSymbolAddress((void**)&g01, g_g01);
    cudaGetSymbolAddress((void**)&gh1, g_gh1);
    cudaGetSymbolAddress((void**)&h0, g_h0);
    cudaGetSymbolAddress((void**)&h1, g_h1);
    cudaGetSymbolAddress((void**)&hb0, g_hb0);
    cudaGetSymbolAddress((void**)&hb1, g_hb1);
    cudaGetSymbolAddress((void**)&hlin, g_hlin);
    cudaGetSymbolAddress((void**)&acc, g_acc);
    cudaGetSymbolAddress((void**)&wb_ih0, g_wb_ih0);
    cudaGetSymbolAddress((void**)&wb_s0, g_wb_s0);
    cudaGetSymbolAddress((void**)&wb_hh1, g_wb_hh1);
    cudaGetSymbolAddress((void**)&wb_a, g_wb_intra);
    cudaGetSymbolAddress((void**)&wb_e, g_wb_inter);
    cudaGetSymbolAddress((void**)&es, g_es);
    cudaGetSymbolAddress((void**)&ed, g_ed);
    cudaGetSymbolAddress((void**)&m, g_m);
    cudaGetSymbolAddress((void**)&deg, g_deg);
    cudaGetSymbolAddress((void**)&off, g_off);
    cudaGetSymbolAddress((void**)&work, g_work);
    cudaGetSymbolAddress((void**)&csrc, g_csrc);
    cudaGetSymbolAddress((void**)&ev, g_ev);
    cudaGetSymbolAddress((void**)&pu, g_pu);
    cudaGetSymbolAddress((void**)&pool, g_pool);
    cudaGetSymbolAddress((void**)&poolb, g_poolb);
    cudaGetSymbolAddress((void**)&shlin, g_shlin);
    cudaGetSymbolAddress((void**)&sacc, g_sacc);

    const int cellGrid = (NN * HH + 255) / 256;

    // ---- prep ----
    convw_k<<<(G3 * INP + 255) / 256, 256>>>(w_ih0, wb_ih0, G3, INP);
    convw_k<<<(NN * TT * INP + 255) / 256, 256>>>(x, xb, NN * TT, INP);
    convw_k<<<(G3 * HH + 255) / 256, 256>>>(w_hh0, wb_s0, G3, HH);
    convw_k<<<(G3 * HH + 255) / 256, 256>>>(w_ih1, wb_s0 + (size_t)G3 * 2 * HH, G3, HH);
    convw_k<<<(G3 * HH + 255) / 256, 256>>>(w_hh1, wb_hh1, G3, HH);
    launch_gemm(xb, wb_ih0, gi, NN * TT, G3, INP);
    zerof_k<<<(NN * HH + 255) / 256, 256>>>(h0, NN * HH);
    zerof_k<<<(NN * HH + 255) / 256, 256>>>(h1, NN * HH);
    zerou_k<<<(NN * HH + 255) / 256, 256>>>((unsigned*)hb0, NN * HH);
    zerou_k<<<(NN * HH + 255) / 256, 256>>>((unsigned*)hb1, NN * HH);
    // build intra CSR early (independent of GRU; hides behind nothing but cheap)
    zerou_k<<<(NN + 255) / 256, 256>>>(deg, NN);
    hist_k<<<(EINTRA + 255) / 256, 256>>>(ei_intra, deg, EINTRA);
    scan_k<<<1, 1024>>>(deg, off, work, NN);
    scatter_k<<<(EINTRA + 255) / 256, 256>>>(ei_intra, work, csrc, EINTRA);

    // ---- pipelined GRU: iteration it = layer0 step it & layer1 step it-1 ----
    const dim3 g2grid(9, (NN + 127) / 128);
    const dim3 cellG(cellGrid, 2);
    for (int it = 0; it <= TT; it++) {
        const int act0 = (it < TT) ? 1 : 0;
        const int act1 = (it >= 1) ? 1 : 0;
        gemm2_k<<<g2grid, 256>>>(hb0, hb1, wb_s0, wb_hh1, g01, gh1, act1);
        cell2_k<<<cellG, 256>>>(gi, g01, gh1, b_ih0, b_hh0, h0, hb0,
                                b_ih1, b_hh1, h1, hb1, it, act0, act1);
    }
    // h1 == seq_emb (fp32), hb1 == its bf16 split

    // ---- intra GAT (CSR) ----
    convw_k<<<(HH * HH + 255) / 256, 256>>>(intra_W, wb_a, HH, HH);
    launch_gemm(hb1, wb_a, hlin, NN, HH, HH);
    gat_scores_k<<<(NN * 32 + 255) / 256, 256>>>(hlin, a_src_i, a_dst_i, es, ed, NN);
    csr_max_k<<<(NN * 32 + 255) / 256, 256>>>(csrc, off, deg, es, ed, ev, m, NN);
    csr_agg_k<<<(NN * 32 + 255) / 256, 256>>>(csrc, off, deg, es, ed, ev, m,
                                              hlin, bias_i, acc, NN);
    // acc == intra_emb

    // ---- sector max pool ----
    zerou_k<<<(SS * HH + 255) / 256, 256>>>(pu, SS * HH);
    pool_max_k<<<(NN * HH + 255) / 256, 256>>>(acc, sid, pu);
    pool_conv_k<<<(SS * HH + 255) / 256, 256>>>(pu, pool, poolb);

    // ---- inter GAT (CSR, S=64) ----
    convw_k<<<(HH * HH + 255) / 256, 256>>>(inter_W, wb_e, HH, HH);
    launch_gemm(poolb, wb_e, shlin, SS, HH, HH);
    gat_scores_k<<<(SS * 32 + 255) / 256, 256>>>(shlin, a_src_e, a_dst_e, es, ed, SS);
    zerou_k<<<(SS + 255) / 256, 256>>>(deg, SS);
    hist_k<<<(EINTER + 255) / 256, 256>>>(ei_inter, deg, EINTER);
    scan_k<<<1, 1024>>>(deg, off, work, SS);
    scatter_k<<<(EINTER + 255) / 256, 256>>>(ei_inter, work, csrc, EINTER);
    csr_max_k<<<(SS * 32 + 255) / 256, 256>>>(csrc, off, deg, es, ed, ev, m, SS);
    csr_agg_k<<<(SS * 32 + 255) / 256, 256>>>(csrc, off, deg, es, ed, ev, m,
                                              shlin, bias_e, sacc, SS);
    // sacc == inter_sec

    // ---- fusion ----
    fusion_k<<<(NN * 32 + 255) / 256, 256>>>(h1, acc, sacc, sid, fw, fb, out);
}

// round 11
// speedup vs baseline: 1.1568x; 1.1568x over previous
#include <cuda_runtime.h>
#include <cuda_fp16.h>
#include <math.h>
#include <stdint.h>

#define NN     20000
#define TT     32
#define INP    64
#define HH     128
#define G3     384
#define SS     64
#define EINTRA 640000
#define EINTER 4096

// ---------------- scratch (static device globals; no allocs) ----------------
__device__ __align__(128) float g_gi[(size_t)NN*TT*G3];            // layer0 gi, 983 MB
__device__ __align__(128) __half g_xb[(size_t)NN*TT*2*INP];        // x split hi|lo fp16
__device__ __align__(128) float g_g01[(size_t)NN*768];             // [gh0 | gi1] fused
__device__ __align__(128) float g_gh1[(size_t)NN*G3];
__device__ __align__(128) float g_h0[(size_t)NN*HH];
__device__ __align__(128) float g_h1[(size_t)NN*HH];
__device__ __align__(128) __half g_hb0[(size_t)NN*2*HH];           // h0 split hi|lo
__device__ __align__(128) __half g_hb1[(size_t)NN*2*HH];           // h1 split hi|lo
__device__ __align__(128) float g_hlin[(size_t)NN*HH];
__device__ __align__(128) float g_acc[(size_t)NN*HH];
__device__ __align__(128) __half g_wb_ih0[G3*INP];                 // single fp16 weights
__device__ __align__(128) __half g_wb_s0[2*G3*HH];                 // [Whh0 ; Wih1] stacked 768x128
__device__ __align__(128) __half g_wb_hh1[G3*HH];
__device__ __align__(128) __half g_wb_intra[HH*HH];
__device__ __align__(128) __half g_wb_inter[HH*HH];
__device__ float    g_es[NN];
__device__ float    g_ed[NN];
__device__ float    g_m[NN];
__device__ unsigned g_deg[NN];
__device__ unsigned g_off[NN];
__device__ unsigned g_work[NN];
__device__ int      g_csrc[EINTRA];
__device__ float    g_ev[EINTRA];
__device__ unsigned g_pu[SS*HH];
__device__ __align__(128) float g_pool[SS*HH];
__device__ __align__(128) __half g_poolb[SS*2*HH];
__device__ __align__(128) float g_shlin[SS*HH];
__device__ __align__(128) float g_sacc[SS*HH];

// ---------------- helpers ----------------
__device__ __forceinline__ uint32_t smem_u32(const void* p) {
    uint32_t a;
    asm("{ .reg .u64 t; cvta.to.shared.u64 t, %1; cvt.u32.u64 %0, t; }" : "=r"(a) : "l"(p));
    return a;
}
__device__ __forceinline__ unsigned fkey(float f) {
    unsigned u = __float_as_uint(f);
    return (u & 0x80000000u) ? ~u : (u | 0x80000000u);
}
__device__ __forceinline__ float funkey(unsigned k) {
    return (k & 0x80000000u) ? __uint_as_float(k & 0x7fffffffu)
                             : __uint_as_float(~k);
}
__device__ __forceinline__ float lrelu(float x) { return x > 0.f ? x : 0.2f * x; }

__device__ __forceinline__ void cp_async16(uint32_t saddr, const void* gaddr, int srcBytes) {
    asm volatile("cp.async.cg.shared.global [%0], [%1], 16, %2;"
                 :: "r"(saddr), "l"(gaddr), "r"(srcBytes) : "memory");
}
__device__ __forceinline__ void cp_commit() {
    asm volatile("cp.async.commit_group;" ::: "memory");
}
template <int N>
__device__ __forceinline__ void cp_wait() {
    asm volatile("cp.async.wait_group %0;" :: "n"(N) : "memory");
}
__device__ __forceinline__ void ldmatrix_x4(uint32_t* r, uint32_t addr) {
    asm volatile("ldmatrix.sync.aligned.m8n8.x4.shared.b16 {%0,%1,%2,%3}, [%4];"
                 : "=r"(r[0]), "=r"(r[1]), "=r"(r[2]), "=r"(r[3]) : "r"(addr));
}
__device__ __forceinline__ void mma16816(float* d, const uint32_t* a, uint32_t b0, uint32_t b1) {
    asm volatile(
        "mma.sync.aligned.m16n8k16.row.col.f32.f16.f16.f32 "
        "{%0,%1,%2,%3}, {%4,%5,%6,%7}, {%8,%9}, {%0,%1,%2,%3};"
        : "+f"(d[0]), "+f"(d[1]), "+f"(d[2]), "+f"(d[3])
        : "r"(a[0]), "r"(a[1]), "r"(a[2]), "r"(a[3]), "r"(b0), "r"(b1));
}

// ---------------- misc kernels ----------------
__global__ void zerof_k(float* p, int n) {
    int i = blockIdx.x * blockDim.x + threadIdx.x;
    if (i < n) p[i] = 0.f;
}
__global__ void zerou_k(unsigned* p, int n) {
    int i = blockIdx.x * blockDim.x + threadIdx.x;
    if (i < n) p[i] = 0u;
}
// weights: fp32 [rows,K] -> single fp16 [rows,K]
__global__ void convw1_k(const float* __restrict__ W, __half* __restrict__ Wb,
                         int rows, int K) {
    int idx = blockIdx.x * blockDim.x + threadIdx.x;
    if (idx >= rows * K) return;
    Wb[idx] = __float2half_rn(W[idx]);
}
// activations: fp32 [rows,K] -> fp16 [rows, 2K] as [hi | lo]
__global__ void conva_k(const float* __restrict__ X, __half* __restrict__ Xb,
                        int rows, int K) {
    int idx = blockIdx.x * blockDim.x + threadIdx.x;
    if (idx >= rows * K) return;
    int r = idx / K, c = idx % K;
    float v = X[idx];
    __half hi = __float2half_rn(v);
    __half lo = __float2half_rn(v - __half2float(hi));
    Xb[(size_t)r * 2 * K + c]     = hi;
    Xb[(size_t)r * 2 * K + K + c] = lo;
}

// ------- tensor-core GEMM body (mma.sync fp16): C = (Ahi + Alo) @ B^T -------
// Ab [M, 2K] fp16 split hi|lo (row stride ldA elems), Bb [Nc, K] single fp16,
// C [M,Nc] fp32. Two passes: Ahi@B^T + Alo@B^T. Tile 128x128xBK32, cp.async
// double buffer, XOR-swizzled smem, 8 warps each 32x64.
__device__ __forceinline__ void gemm_body(
    char* smbuf,
    const __half* __restrict__ Ab, int ldA,
    const __half* __restrict__ Bb,
    float* __restrict__ C, int M, int Nc, int K, int bm, int bn)
{
    const uint32_t sb = smem_u32(smbuf);
    const int tid = threadIdx.x;
    const int wid = tid >> 5, lane = tid & 31;
    const int wm = wid & 3;
    const int wn = wid >> 2;
    const int ldB = K;

    const int cpk = K >> 5;
    const int nk = 2 * cpk;                 // 2 segments: A-hi, A-lo

    float d[2][8][4];
#pragma unroll
    for (int i = 0; i < 2; i++)
#pragma unroll
        for (int j = 0; j < 8; j++)
#pragma unroll
            for (int q = 0; q < 4; q++) d[i][j][q] = 0.f;

    auto issue_loads = [&](int kb, int s) {
        const int seg = kb / cpk, kc = kb - seg * cpk;
        const int acol = (seg == 1 ? K : 0) + (kc << 5);
        const int bcol = kc << 5;
        const __half* Abase = Ab + acol;
        const __half* Bbase = Bb + bcol;
        const uint32_t sA = sb + s * 16384;
        const uint32_t sB = sA + 8192;
#pragma unroll
        for (int i = 0; i < 2; i++) {
            int cid = tid + (i << 8);
            int r = cid >> 2, c = cid & 3;
            uint32_t soff = (uint32_t)(r << 6) + (uint32_t)((c ^ ((r >> 1) & 3)) << 4);
            int arow = bm + r;
            const char* ga = (const char*)(Abase + (size_t)(arow < M ? arow : 0) * ldA) + (c << 4);
            cp_async16(sA + soff, ga, arow < M ? 16 : 0);
            const char* gb = (const char*)(Bbase + (size_t)(bn + r) * ldB) + (c << 4);
            cp_async16(sB + soff, gb, 16);
        }
        cp_commit();
    };

    issue_loads(0, 0);

    for (int kb = 0; kb < nk; kb++) {
        const int s = kb & 1;
        if (kb + 1 < nk) issue_loads(kb + 1, s ^ 1);
        if (kb + 1 < nk) cp_wait<1>(); else cp_wait<0>();
        __syncthreads();

        const uint32_t sA = sb + s * 16384;
        const uint32_t sB = sA + 8192;
        const int lr = lane & 15;
        const int lk = (lane >> 4) << 4;
#pragma unroll
        for (int k16 = 0; k16 < 2; k16++) {
            const int kby = (k16 << 5) + lk;
            const int csel = kby >> 4;
            uint32_t a[2][4], bf[4][4];
#pragma unroll
            for (int mt = 0; mt < 2; mt++) {
                int r = wm * 32 + mt * 16 + lr;
                uint32_t addr = sA + (uint32_t)(r << 6) + (uint32_t)((csel ^ ((r >> 1) & 3)) << 4);
                ldmatrix_x4(a[mt], addr);
            }
#pragma unroll
            for (int p = 0; p < 4; p++) {
                int r = wn * 64 + p * 16 + lr;
                uint32_t addr = sB + (uint32_t)(r << 6) + (uint32_t)((csel ^ ((r >> 1) & 3)) << 4);
                ldmatrix_x4(bf[p], addr);
            }
#pragma unroll
            for (int mt = 0; mt < 2; mt++)
#pragma unroll
                for (int nt = 0; nt < 8; nt++) {
                    int p = nt >> 1, hi = nt & 1;
                    mma16816(d[mt][nt], a[mt], bf[p][hi], bf[p][2 + hi]);
                }
        }
        __syncthreads();
    }

    const int gr = lane >> 2;
    const int gc = (lane & 3) << 1;
#pragma unroll
    for (int mt = 0; mt < 2; mt++) {
        int r0 = bm + wm * 32 + mt * 16 + gr;
#pragma unroll
        for (int nt = 0; nt < 8; nt++) {
            int cc = bn + wn * 64 + nt * 8 + gc;
            if (r0 < M)
                *(float2*)(C + (size_t)r0 * Nc + cc) = make_float2(d[mt][nt][0], d[mt][nt][1]);
            if (r0 + 8 < M)
                *(float2*)(C + (size_t)(r0 + 8) * Nc + cc) = make_float2(d[mt][nt][2], d[mt][nt][3]);
        }
    }
}

// single-problem GEMM kernel
__global__ void __launch_bounds__(256) gemm_mma_k(
    const __half* __restrict__ Ab, int ldA,
    const __half* __restrict__ Bb,
    float* __restrict__ C, int M, int Nc, int K)
{
    __shared__ __align__(16) char smbuf[32768];
    gemm_body(smbuf, Ab, ldA, Bb, C, M, Nc, K, blockIdx.y * 128, blockIdx.x * 128);
}

// recurrent-step GEMM: bx 0..5: [gh0|gi1] = hb0 @ [Whh0;Wih1]^T (Nc=768);
//                      bx 6..8: gh1 = hb1 @ Whh1^T (Nc=384), only if act1.
__global__ void __launch_bounds__(256) gemm2_k(
    const __half* __restrict__ hb0,
    const __half* __restrict__ hb1,
    const __half* __restrict__ Bs0,
    const __half* __restrict__ Bhh1,
    float* __restrict__ g01, float* __restrict__ gh1, int act1)
{
    __shared__ __align__(16) char smbuf[32768];
    const int bx = blockIdx.x;
    const int bm = blockIdx.y * 128;
    if (bx < 6) {
        gemm_body(smbuf, hb0, 2 * HH, Bs0, g01, NN, 768, HH, bm, bx * 128);
    } else {
        if (!act1) return;
        gemm_body(smbuf, hb1, 2 * HH, Bhh1, gh1, NN, G3, HH, bm, (bx - 6) * 128);
    }
}

// ---------------- dual-layer GRU pointwise cell ----------------
__global__ void cell2_k(const float* __restrict__ gi0, const float* __restrict__ g01,
                        const float* __restrict__ gh1,
                        const float* __restrict__ bih0, const float* __restrict__ bhh0,
                        float* __restrict__ h0, __half* __restrict__ hb0,
                        const float* __restrict__ bih1, const float* __restrict__ bhh1,
                        float* __restrict__ h1, __half* __restrict__ hb1,
                        int t0, int act0, int act1) {
    int idx = blockIdx.x * blockDim.x + threadIdx.x;
    if (idx >= NN * HH) return;
    int i = idx >> 7;
    int j = idx & 127;
    if (blockIdx.y == 0) {
        if (!act0) return;
        size_t mg = ((size_t)i * TT + t0) * G3;
        size_t hg = (size_t)i * 768;
        float ir  = gi0[mg + j]          + bih0[j];
        float iz  = gi0[mg + HH + j]     + bih0[HH + j];
        float inn = gi0[mg + 2 * HH + j] + bih0[2 * HH + j];
        float hr  = g01[hg + j]          + bhh0[j];
        float hz  = g01[hg + HH + j]     + bhh0[HH + j];
        float hn  = g01[hg + 2 * HH + j] + bhh0[2 * HH + j];
        float r = 1.f / (1.f + expf(-(ir + hr)));
        float z = 1.f / (1.f + expf(-(iz + hz)));
        float n = tanhf(inn + r * hn);
        float hold = h0[idx];
        float hnew = (1.f - z) * n + z * hold;
        h0[idx] = hnew;
        __half hi = __float2half_rn(hnew);
        __half lo = __float2half_rn(hnew - __half2float(hi));
        hb0[(size_t)i * 256 + j]      = hi;
        hb0[(size_t)i * 256 + HH + j] = lo;
    } else {
        if (!act1) return;
        size_t ig = (size_t)i * 768 + 384;     // gi1 slice of g01
        size_t hg = (size_t)i * G3;
        float ir  = g01[ig + j]          + bih1[j];
        float iz  = g01[ig + HH + j]     + bih1[HH + j];
        float inn = g01[ig + 2 * HH + j] + bih1[2 * HH + j];
        float hr  = gh1[hg + j]          + bhh1[j];
        float hz  = gh1[hg + HH + j]     + bhh1[HH + j];
        float hn  = gh1[hg + 2 * HH + j] + bhh1[2 * HH + j];
        float r = 1.f / (1.f + expf(-(ir + hr)));
        float z = 1.f / (1.f + expf(-(iz + hz)));
        float n = tanhf(inn + r * hn);
        float hold = h1[idx];
        float hnew = (1.f - z) * n + z * hold;
        h1[idx] = hnew;
        __half hi = __float2half_rn(hnew);
        __half lo = __float2half_rn(hnew - __half2float(hi));
        hb1[(size_t)i * 256 + j]      = hi;
        hb1[(size_t)i * 256 + HH + j] = lo;
    }
}

// ---------------- GAT kernels (CSR, no fp32 atomics) ----------------
__global__ void gat_scores_k(const float* __restrict__ hlin,
                             const float* __restrict__ asrc, const float* __restrict__ adst,
                             float* __restrict__ es, float* __restrict__ ed, int n) {
    int g = blockIdx.x * blockDim.x + threadIdx.x;
    int node = g >> 5;
    int lane = g & 31;
    if (node >= n) return;
    float4 h4 = reinterpret_cast<const float4*>(hlin + (size_t)node * HH)[lane];
    float4 a4 = reinterpret_cast<const float4*>(asrc)[lane];
    float4 d4 = reinterpret_cast<const float4*>(adst)[lane];
    float s = h4.x * a4.x + h4.y * a4.y + h4.z * a4.z + h4.w * a4.w;
    float d = h4.x * d4.x + h4.y * d4.y + h4.z * d4.z + h4.w * d4.w;
#pragma unroll
    for (int o = 16; o; o >>= 1) {
        s += __shfl_xor_sync(0xffffffffu, s, o);
        d += __shfl_xor_sync(0xffffffffu, d, o);
    }
    if (lane == 0) {
        es[node] = s;
        ed[node] = d;
    }
}

__global__ void hist_k(const int* __restrict__ ei, unsigned* __restrict__ deg, int E) {
    int e = blockIdx.x * blockDim.x + threadIdx.x;
    if (e < E) atomicAdd(&deg[ei[E + e]], 1u);
}

// one block, 1024 threads: exclusive scan deg[0..n) -> off, copy to work
__global__ void __launch_bounds__(1024) scan_k(const unsigned* __restrict__ deg,
                                               unsigned* __restrict__ off,
                                               unsigned* __restrict__ work, int n) {
    __shared__ unsigned part[1024];
    int t = threadIdx.x;
    int chunk = (n + 1023) / 1024;
    int b = t * chunk;
    int e = b + chunk < n ? b + chunk : n;
    unsigned s = 0;
    for (int i = b; i < e; i++) s += deg[i];
    part[t] = s;
    __syncthreads();
    for (int o = 1; o < 1024; o <<= 1) {
        unsigned v = (t >= o) ? part[t - o] : 0u;
        __syncthreads();
        part[t] += v;
        __syncthreads();
    }
    unsigned run = (t == 0) ? 0u : part[t - 1];
    for (int i = b; i < e; i++) {
        unsigned d = deg[i];
        off[i] = run;
        work[i] = run;
        run += d;
    }
}

__global__ void scatter_k(const int* __restrict__ ei, unsigned* __restrict__ work,
                          int* __restrict__ csrc, int E) {
    int e = blockIdx.x * blockDim.x + threadIdx.x;
    if (e >= E) return;
    int s = ei[e];
    int d = ei[E + e];
    unsigned p = atomicAdd(&work[d], 1u);
    csrc[p] = s;
}

// warp per node: segment max (incl. self loop) + per-edge leaky-relu scores
__global__ void csr_max_k(const int* __restrict__ csrc, const unsigned* __restrict__ off,
                          const unsigned* __restrict__ deg,
                          const float* __restrict__ es, const float* __restrict__ ed,
                          float* __restrict__ ev, float* __restrict__ m, int n) {
    int g = blockIdx.x * blockDim.x + threadIdx.x;
    int node = g >> 5;
    int lane = g & 31;
    if (node >= n) return;
    float edv = ed[node];
    float mx = lrelu(es[node] + edv);           // self loop
    unsigned o = off[node], dg = deg[node];
    for (unsigned k = lane; k < dg; k += 32) {
        float v = lrelu(es[csrc[o + k]] + edv);
        ev[o + k] = v;
        mx = fmaxf(mx, v);
    }
#pragma unroll
    for (int o2 = 16; o2; o2 >>= 1) mx = fmaxf(mx, __shfl_xor_sync(0xffffffffu, mx, o2));
    if (lane == 0) m[node] = mx;
}

// warp per node: softmax-weighted aggregation, bias, final write (no atomics)
__global__ void csr_agg_k(const int* __restrict__ csrc, const unsigned* __restrict__ off,
                          const unsigned* __restrict__ deg,
                          const float* __restrict__ es, const float* __restrict__ ed,
                          const float* __restrict__ ev, const float* __restrict__ m,
                          const float* __restrict__ hlin, const float* __restrict__ bias,
                          float* __restrict__ outp, int n) {
    int g = blockIdx.x * blockDim.x + threadIdx.x;
    int node = g >> 5;
    int lane = g & 31;
    if (node >= n) return;
    float mv = m[node];
    float w0 = expf(lrelu(es[node] + ed[node]) - mv);
    float den = w0;
    float4 hv = reinterpret_cast<const float4*>(hlin + (size_t)node * HH)[lane];
    float4 a = make_float4(w0 * hv.x, w0 * hv.y, w0 * hv.z, w0 * hv.w);
    unsigned o = off[node], dg = deg[node];
    for (unsigned k = 0; k < dg; k++) {
        float w = expf(ev[o + k] - mv);
        int s = csrc[o + k];
        float4 h4 = reinterpret_cast<const float4*>(hlin + (size_t)s * HH)[lane];
        a.x += w * h4.x; a.y += w * h4.y; a.z += w * h4.z; a.w += w * h4.w;
        den += w;
    }
    float4 b4 = reinterpret_cast<const float4*>(bias)[lane];
    float inv = 1.f / den;
    reinterpret_cast<float4*>(outp + (size_t)node * HH)[lane] =
        make_float4(a.x * inv + b4.x, a.y * inv + b4.y, a.z * inv + b4.z, a.w * inv + b4.w);
}

// ---------------- sector max pool ----------------
__global__ void pool_max_k(const float* __restrict__ x, const int* __restrict__ sid,
                           unsigned* __restrict__ pu) {
    int idx = blockIdx.x * blockDim.x + threadIdx.x;
    if (idx >= NN * HH) return;
    int i = idx >> 7;
    int j = idx & 127;
    atomicMax(&pu[sid[i] * HH + j], fkey(x[idx]));
}
__global__ void pool_conv_k(const unsigned* __restrict__ pu, float* __restrict__ p,
                            __half* __restrict__ pb) {
    int idx = blockIdx.x * blockDim.x + threadIdx.x;
    if (idx >= SS * HH) return;
    int r = idx >> 7, j = idx & 127;
    float v = funkey(pu[idx]);
    p[idx] = v;
    __half hi = __float2half_rn(v);
    __half lo = __float2half_rn(v - __half2float(hi));
    pb[(size_t)r * 2 * HH + j]      = hi;
    pb[(size_t)r * 2 * HH + HH + j] = lo;
}

// ---------------- fusion head ----------------
__global__ void fusion_k(const float* __restrict__ seq, const float* __restrict__ intra,
                         const float* __restrict__ inter, const int* __restrict__ sid,
                         const float* __restrict__ fw, const float* __restrict__ fb,
                         float* __restrict__ out) {
    int g = blockIdx.x * blockDim.x + threadIdx.x;
    int i = g >> 5;
    int lane = g & 31;
    if (i >= NN) return;
    int sc = sid[i];
    const float4* s4 = reinterpret_cast<const float4*>(seq + (size_t)i * HH);
    const float4* i4 = reinterpret_cast<const float4*>(intra + (size_t)i * HH);
    const float4* e4 = reinterpret_cast<const float4*>(inter + (size_t)sc * HH);
    const float4* w4 = reinterpret_cast<const float4*>(fw);
    float sum = 0.f;
    float4 a, b;
    a = s4[lane]; b = w4[lane];
    sum += a.x * b.x + a.y * b.y + a.z * b.z + a.w * b.w;
    a = i4[lane]; b = w4[32 + lane];
    sum += a.x * b.x + a.y * b.y + a.z * b.z + a.w * b.w;
    a = e4[lane]; b = w4[64 + lane];
    sum += a.x * b.x + a.y * b.y + a.z * b.z + a.w * b.w;
#pragma unroll
    for (int o = 16; o; o >>= 1) sum += __shfl_xor_sync(0xffffffffu, sum, o);
    if (lane == 0) out[i] = sum + fb[0];
}

// ---------------- host ----------------
static inline void launch_gemm(const __half* Ab, const __half* Bb,
                               float* C, int M, int Nc, int K) {
    dim3 grid(Nc / 128, (M + 127) / 128);
    gemm_mma_k<<<grid, 256>>>(Ab, 2 * K, Bb, C, M, Nc, K);
}

extern "C" void kernel_launch(void* const* d_in, const int* in_sizes, int n_in,
                              void* d_out, int out_size) {
    const float* x        = (const float*)d_in[0];
    const int*   ei_intra = (const int*)d_in[1];
    const int*   ei_inter = (const int*)d_in[2];
    const int*   sid      = (const int*)d_in[3];
    const float* w_ih0 = (const float*)d_in[4];
    const float* w_hh0 = (const float*)d_in[5];
    const float* b_ih0 = (const float*)d_in[6];
    const float* b_hh0 = (const float*)d_in[7];
    const float* w_ih1 = (const float*)d_in[8];
    const float* w_hh1 = (const float*)d_in[9];
    const float* b_ih1 = (const float*)d_in[10];
    const float* b_hh1 = (const float*)d_in[11];
    const float* intra_W  = (const float*)d_in[12];
    const float* a_src_i  = (const float*)d_in[13];
    const float* a_dst_i  = (const float*)d_in[14];
    const float* bias_i   = (const float*)d_in[15];
    const float* inter_W  = (const float*)d_in[16];
    const float* a_src_e  = (const float*)d_in[17];
    const float* a_dst_e  = (const float*)d_in[18];
    const float* bias_e   = (const float*)d_in[19];
    const float* fw       = (const float*)d_in[20];
    const float* fb       = (const float*)d_in[21];
    float* out = (float*)d_out;

    float *gi, *g01, *gh1, *h0, *h1, *hlin, *acc;
    float *es, *ed, *m, *ev, *pool, *shlin, *sacc;
    __half *xb, *hb0, *hb1, *wb_ih0, *wb_s0, *wb_hh1, *wb_a, *wb_e, *poolb;
    unsigned *deg, *off, *work, *pu;
    int *csrc;
    cudaGetSymbolAddress((void**)&gi, g_gi);
    cudaGetSymbolAddress((void**)&xb, g_xb);
    cudaGetSymbolAddress((void**)&g01, g_g01);
    cudaGetSymbolAddress((void**)&gh1, g_gh1);
    cudaGetSymbolAddress((void**)&h0, g_h0);
    cudaGetSymbolAddress((void**)&h1, g_h1);
    cudaGetSymbolAddress((void**)&hb0, g_hb0);
    cudaGetSymbolAddress((void**)&hb1, g_hb1);
    cudaGetSymbolAddress((void**)&hlin, g_hlin);
    cudaGetSymbolAddress((void**)&acc, g_acc);
    cudaGetSymbolAddress((void**)&wb_ih0, g_wb_ih0);
    cudaGetSymbolAddress((void**)&wb_s0, g_wb_s0);
    cudaGetSymbolAddress((void**)&wb_hh1, g_wb_hh1);
    cudaGetSymbolAddress((void**)&wb_a, g_wb_intra);
    cudaGetSymbolAddress((void**)&wb_e, g_wb_inter);
    cudaGetSymbolAddress((void**)&es, g_es);
    cudaGetSymbolAddress((void**)&ed, g_ed);
    cudaGetSymbolAddress((void**)&m, g_m);
    cudaGetSymbolAddress((void**)&deg, g_deg);
    cudaGetSymbolAddress((void**)&off, g_off);
    cudaGetSymbolAddress((void**)&work, g_work);
    cudaGetSymbolAddress((void**)&csrc, g_csrc);
    cudaGetSymbolAddress((void**)&ev, g_ev);
    cudaGetSymbolAddress((void**)&pu, g_pu);
    cudaGetSymbolAddress((void**)&pool, g_pool);
    cudaGetSymbolAddress((void**)&poolb, g_poolb);
    cudaGetSymbolAddress((void**)&shlin, g_shlin);
    cudaGetSymbolAddress((void**)&sacc, g_sacc);

    const int cellGrid = (NN * HH + 255) / 256;

    // ---- prep ----
    convw1_k<<<(G3 * INP + 255) / 256, 256>>>(w_ih0, wb_ih0, G3, INP);
    conva_k<<<(NN * TT * INP + 255) / 256, 256>>>(x, xb, NN * TT, INP);
    convw1_k<<<(G3 * HH + 255) / 256, 256>>>(w_hh0, wb_s0, G3, HH);
    convw1_k<<<(G3 * HH + 255) / 256, 256>>>(w_ih1, wb_s0 + (size_t)G3 * HH, G3, HH);
    convw1_k<<<(G3 * HH + 255) / 256, 256>>>(w_hh1, wb_hh1, G3, HH);
    launch_gemm(xb, wb_ih0, gi, NN * TT, G3, INP);
    zerof_k<<<(NN * HH + 255) / 256, 256>>>(h0, NN * HH);
    zerof_k<<<(NN * HH + 255) / 256, 256>>>(h1, NN * HH);
    zerou_k<<<(NN * HH + 255) / 256, 256>>>((unsigned*)hb0, NN * HH);
    zerou_k<<<(NN * HH + 255) / 256, 256>>>((unsigned*)hb1, NN * HH);
    // build intra CSR early
    zerou_k<<<(NN + 255) / 256, 256>>>(deg, NN);
    hist_k<<<(EINTRA + 255) / 256, 256>>>(ei_intra, deg, EINTRA);
    scan_k<<<1, 1024>>>(deg, off, work, NN);
    scatter_k<<<(EINTRA + 255) / 256, 256>>>(ei_intra, work, csrc, EINTRA);

    // ---- pipelined GRU: iteration it = layer0 step it & layer1 step it-1 ----
    const dim3 g2grid(9, (NN + 127) / 128);
    const dim3 cellG(cellGrid, 2);
    for (int it = 0; it <= TT; it++) {
        const int act0 = (it < TT) ? 1 : 0;
        const int act1 = (it >= 1) ? 1 : 0;
        gemm2_k<<<g2grid, 256>>>(hb0, hb1, wb_s0, wb_hh1, g01, gh1, act1);
        cell2_k<<<cellG, 256>>>(gi, g01, gh1, b_ih0, b_hh0, h0, hb0,
                                b_ih1, b_hh1, h1, hb1, it, act0, act1);
    }
    // h1 == seq_emb (fp32), hb1 == its fp16 split

    // ---- intra GAT (CSR) ----
    convw1_k<<<(HH * HH + 255) / 256, 256>>>(intra_W, wb_a, HH, HH);
    launch_gemm(hb1, wb_a, hlin, NN, HH, HH);
    gat_scores_k<<<(NN * 32 + 255) / 256, 256>>>(hlin, a_src_i, a_dst_i, es, ed, NN);
    csr_max_k<<<(NN * 32 + 255) / 256, 256>>>(csrc, off, deg, es, ed, ev, m, NN);
    csr_agg_k<<<(NN * 32 + 255) / 256, 256>>>(csrc, off, deg, es, ed, ev, m,
                                              hlin, bias_i, acc, NN);
    // acc == intra_emb

    // ---- sector max pool ----
    zerou_k<<<(SS * HH + 255) / 256, 256>>>(pu, SS * HH);
    pool_max_k<<<(NN * HH + 255) / 256, 256>>>(acc, sid, pu);
    pool_conv_k<<<(SS * HH + 255) / 256, 256>>>(pu, pool, poolb);

    // ---- inter GAT (CSR, S=64) ----
    convw1_k<<<(HH * HH + 255) / 256, 256>>>(inter_W, wb_e, HH, HH);
    launch_gemm(poolb, wb_e, shlin, SS, HH, HH);
    gat_scores_k<<<(SS * 32 + 255) / 256, 256>>>(shlin, a_src_e, a_dst_e, es, ed, SS);
    zerou_k<<<(SS + 255) / 256, 256>>>(deg, SS);
    hist_k<<<(EINTER + 255) / 256, 256>>>(ei_inter, deg, EINTER);
    scan_k<<<1, 1024>>>(deg, off, work, SS);
    scatter_k<<<(EINTER + 255) / 256, 256>>>(ei_inter, work, csrc, EINTER);
    csr_max_k<<<(SS * 32 + 255) / 256, 256>>>(csrc, off, deg, es, ed, ev, m, SS);
    csr_agg_k<<<(SS * 32 + 255) / 256, 256>>>(csrc, off, deg, es, ed, ev, m,
                                              shlin, bias_e, sacc, SS);
    // sacc == inter_sec

    // ---- fusion ----
    fusion_k<<<(NN * 32 + 255) / 256, 256>>>(h1, acc, sacc, sid, fw, fb, out);
}